// round 8
// baseline (speedup 1.0000x reference)
#include <cuda_runtime.h>
#include <cuda_fp16.h>
#include <cstdint>

// AntisymmetricLayer via fp16 mma.sync.m16n8k16 (fp32 accum).
//   z = x1-x2, s = x1+x2 (fp16)
//   Phase L: lin = z @ W^T -> out (W fragment-packed per warp, ownership matches epilogue)
//   Main: per 4-k group, zP = z @ P^T, sQ = s @ Q^T; epilogue RMW out += sum_r zP*sQ
// r8: MTILE=64, 4 warps (2Mx2N, warp tile 32x32), 32KB smem, 3 CTAs/SM (12 warps) ->
// better latency hiding + 5-wave schedule (8% tail vs 15.7%). B fragments straight
// from L2 (packed), no cp.async, no main-loop barriers.

#define D128 128
#define KTOT 64
#define MTILE 64
#define NGRP 16
#define THREADS 128

#define ZSH 0
#define SSH 16384
#define SMEM_BYTES 32768

// fragment-packed B: [g][ks][wn][j] blocks of 512B (32 lanes x 16B = P.b0,b1,Q.b0,b1)
__device__ __align__(16) __half g_B[16 * 8 * 2 * 4 * 256];
// fragment-packed W: [ks][wn][t] blocks of 256B (32 lanes x 8B)
__device__ __align__(16) __half g_Wt[8 * 2 * 4 * 128];

__device__ __forceinline__ uint32_t smem_u32(const void* p) {
    uint32_t a;
    asm("{ .reg .u64 t; cvta.to.shared.u64 t, %1; cvt.u32.u64 %0, t; }" : "=r"(a) : "l"(p));
    return a;
}

#define LDSM_X4(r0, r1, r2, r3, a) \
    asm volatile("ldmatrix.sync.aligned.m8n8.x4.shared.b16 {%0,%1,%2,%3}, [%4];" \
        : "=r"(r0), "=r"(r1), "=r"(r2), "=r"(r3) : "r"(a))

__device__ __forceinline__ void mma_f16(float* d, const uint32_t* a, const uint32_t* b) {
    asm volatile("mma.sync.aligned.m16n8k16.row.col.f32.f16.f16.f32 "
                 "{%0,%1,%2,%3}, {%4,%5,%6,%7}, {%8,%9}, {%0,%1,%2,%3};"
                 : "+f"(d[0]), "+f"(d[1]), "+f"(d[2]), "+f"(d[3])
                 : "r"(a[0]), "r"(a[1]), "r"(a[2]), "r"(a[3]),
                   "r"(b[0]), "r"(b[1]));
}

// ---- pack P,Q into fragment order ----
__global__ void pack_b(const float* __restrict__ P, const float* __restrict__ Q) {
    int t = blockIdx.x * 256 + threadIdx.x;   // 0..32767
    int l = t & 31, j = (t >> 5) & 3, wn = (t >> 7) & 1, ks = (t >> 8) & 7, g = t >> 11;
    int c = wn * 32 + j * 8 + (l >> 2);
    int k = g * 4 + (c >> 4), r = c & 15;
    int d0 = ks * 16 + 2 * (l & 3);
    __half h[8];
    h[0] = __float2half_rn(P[(k * 128 + d0) * 16 + r]);
    h[1] = __float2half_rn(P[(k * 128 + d0 + 1) * 16 + r]);
    h[2] = __float2half_rn(P[(k * 128 + d0 + 8) * 16 + r]);
    h[3] = __float2half_rn(P[(k * 128 + d0 + 9) * 16 + r]);
    h[4] = __float2half_rn(Q[(k * 128 + d0) * 16 + r]);
    h[5] = __float2half_rn(Q[(k * 128 + d0 + 1) * 16 + r]);
    h[6] = __float2half_rn(Q[(k * 128 + d0 + 8) * 16 + r]);
    h[7] = __float2half_rn(Q[(k * 128 + d0 + 9) * 16 + r]);
    *reinterpret_cast<uint4*>(&g_B[t * 8]) = *reinterpret_cast<uint4*>(h);
}

// ---- pack W ----
__global__ void pack_w(const float* __restrict__ W) {
    int t = blockIdx.x * 256 + threadIdx.x;   // 0..2047
    int l = t & 31, tile = (t >> 5) & 3, wn = (t >> 7) & 1, ks = t >> 8;
    int n = l >> 2;
    int k = 16 * tile + 4 * (n >> 1) + 2 * wn + (n & 1);
    int d0 = ks * 16 + 2 * (l & 3);
    __half h[4];
    h[0] = __float2half_rn(W[k * 128 + d0]);
    h[1] = __float2half_rn(W[k * 128 + d0 + 1]);
    h[2] = __float2half_rn(W[k * 128 + d0 + 8]);
    h[3] = __float2half_rn(W[k * 128 + d0 + 9]);
    *reinterpret_cast<uint2*>(&g_Wt[t * 4]) = *reinterpret_cast<uint2*>(h);
}

// ---------------- main kernel ----------------
__global__ __launch_bounds__(THREADS, 3)
void antisym_h(const float* __restrict__ x1, const float* __restrict__ x2,
               float* __restrict__ out)
{
    extern __shared__ char shm[];
    const uint32_t smb = smem_u32(shm);
    const int tid = threadIdx.x;
    const int lane = tid & 31;
    const int wid = tid >> 5;
    const int wm = wid & 1;        // M-warp 0..1 (32 tokens each)
    const int wn = wid >> 1;       // N-warp 0..1
    const int g4 = lane >> 2;
    const int c4 = lane & 3;
    const int mbase = blockIdx.x * MTILE;

    // ---- stage z,s as fp16 (swizzled 256B rows), once ----
    {
        const float4* x1v = reinterpret_cast<const float4*>(x1) + (size_t)mbase * 32;
        const float4* x2v = reinterpret_cast<const float4*>(x2) + (size_t)mbase * 32;
        #pragma unroll
        for (int it = 0; it < 8; it++) {
            int idx = it * THREADS + tid;            // 1024 chunks
            int m = idx >> 4, c = idx & 15;
            float4 a0 = x1v[m * 32 + c * 2];
            float4 a1 = x1v[m * 32 + c * 2 + 1];
            float4 b0 = x2v[m * 32 + c * 2];
            float4 b1 = x2v[m * 32 + c * 2 + 1];
            half2 zz[4], ss[4];
            zz[0] = __floats2half2_rn(a0.x - b0.x, a0.y - b0.y);
            zz[1] = __floats2half2_rn(a0.z - b0.z, a0.w - b0.w);
            zz[2] = __floats2half2_rn(a1.x - b1.x, a1.y - b1.y);
            zz[3] = __floats2half2_rn(a1.z - b1.z, a1.w - b1.w);
            ss[0] = __floats2half2_rn(a0.x + b0.x, a0.y + b0.y);
            ss[1] = __floats2half2_rn(a0.z + b0.z, a0.w + b0.w);
            ss[2] = __floats2half2_rn(a1.x + b1.x, a1.y + b1.y);
            ss[3] = __floats2half2_rn(a1.z + b1.z, a1.w + b1.w);
            uint32_t so = (uint32_t)(m * 256 + ((c ^ (m & 7)) << 4));
            *reinterpret_cast<uint4*>(shm + ZSH + so) = *reinterpret_cast<uint4*>(zz);
            *reinterpret_cast<uint4*>(shm + SSH + so) = *reinterpret_cast<uint4*>(ss);
        }
    }
    __syncthreads();   // the ONLY barrier

    // ---- per-lane A ldmatrix row bases ----
    const int xr = lane & 7;
    uint32_t rowA[2];
    #pragma unroll
    for (int mi = 0; mi < 2; mi++)
        rowA[mi] = (uint32_t)((wm * 32 + mi * 16 + ((lane >> 3) & 1) * 8 + xr) * 256);
    const int krelA = lane >> 4;

    const uint4* bv = reinterpret_cast<const uint4*>(g_B);
    const uint2* wv = reinterpret_cast<const uint2*>(g_Wt);

    // ---- Phase L: lin = z @ W^T (per-warp packed W), store to out ----
    {
        float lw[2][4][4] = {};
        #pragma unroll
        for (int ks = 0; ks < 8; ks++) {
            uint32_t offA = (uint32_t)(((2 * ks + krelA) ^ xr) << 4);
            uint32_t az[2][4];
            #pragma unroll
            for (int mi = 0; mi < 2; mi++)
                LDSM_X4(az[mi][0], az[mi][1], az[mi][2], az[mi][3],
                        smb + ZSH + rowA[mi] + offA);
            #pragma unroll
            for (int t = 0; t < 4; t++) {
                uint2 w = wv[((ks * 2 + wn) * 4 + t) * 32 + lane];
                uint32_t bw[2] = {w.x, w.y};
                #pragma unroll
                for (int mi = 0; mi < 2; mi++)
                    mma_f16(lw[mi][t], az[mi], bw);
            }
        }
        #pragma unroll
        for (int mi = 0; mi < 2; mi++) {
            int m0 = mbase + wm * 32 + mi * 16 + g4;
            #pragma unroll
            for (int t = 0; t < 4; t++) {
                int k0 = 16 * t + 4 * c4 + 2 * wn;
                *reinterpret_cast<float2*>(&out[(size_t)m0 * KTOT + k0]) =
                    make_float2(lw[mi][t][0], lw[mi][t][1]);
                *reinterpret_cast<float2*>(&out[(size_t)(m0 + 8) * KTOT + k0]) =
                    make_float2(lw[mi][t][2], lw[mi][t][3]);
            }
        }
    }

    // ---- main loop: no barriers, B straight from L2 ----
    for (int g = 0; g < NGRP; g++) {
        float zp[2][4][4] = {};
        float sq[2][4][4] = {};

        #pragma unroll
        for (int ks = 0; ks < 8; ks++) {
            uint4 v[4];
            const int bb = ((g * 8 + ks) * 2 + wn) * 4;
            #pragma unroll
            for (int j = 0; j < 4; j++) v[j] = bv[(bb + j) * 32 + lane];

            uint32_t offA = (uint32_t)(((2 * ks + krelA) ^ xr) << 4);
            uint32_t az[2][4], as_[2][4];
            #pragma unroll
            for (int mi = 0; mi < 2; mi++) {
                LDSM_X4(az[mi][0], az[mi][1], az[mi][2], az[mi][3],
                        smb + ZSH + rowA[mi] + offA);
                LDSM_X4(as_[mi][0], as_[mi][1], as_[mi][2], as_[mi][3],
                        smb + SSH + rowA[mi] + offA);
            }
            #pragma unroll
            for (int j = 0; j < 4; j++) {
                uint32_t bp[2] = {v[j].x, v[j].y};
                uint32_t bq[2] = {v[j].z, v[j].w};
                #pragma unroll
                for (int mi = 0; mi < 2; mi++) {
                    mma_f16(zp[mi][j], az[mi], bp);
                    mma_f16(sq[mi][j], as_[mi], bq);
                }
            }
        }

        // ---- epilogue: reduce r, RMW out (same lane wrote lin -> no fence) ----
        const int kA = g * 4 + 2 * wn;
        const bool writer = (c4 == (g & 3));
        #pragma unroll
        for (int mi = 0; mi < 2; mi++) {
            float pa0 = zp[mi][0][0]*sq[mi][0][0] + zp[mi][0][1]*sq[mi][0][1]
                      + zp[mi][1][0]*sq[mi][1][0] + zp[mi][1][1]*sq[mi][1][1];
            float pa1 = zp[mi][0][2]*sq[mi][0][2] + zp[mi][0][3]*sq[mi][0][3]
                      + zp[mi][1][2]*sq[mi][1][2] + zp[mi][1][3]*sq[mi][1][3];
            float pb0 = zp[mi][2][0]*sq[mi][2][0] + zp[mi][2][1]*sq[mi][2][1]
                      + zp[mi][3][0]*sq[mi][3][0] + zp[mi][3][1]*sq[mi][3][1];
            float pb1 = zp[mi][2][2]*sq[mi][2][2] + zp[mi][2][3]*sq[mi][2][3]
                      + zp[mi][3][2]*sq[mi][3][2] + zp[mi][3][3]*sq[mi][3][3];
            pa0 += __shfl_xor_sync(~0u, pa0, 1); pa0 += __shfl_xor_sync(~0u, pa0, 2);
            pa1 += __shfl_xor_sync(~0u, pa1, 1); pa1 += __shfl_xor_sync(~0u, pa1, 2);
            pb0 += __shfl_xor_sync(~0u, pb0, 1); pb0 += __shfl_xor_sync(~0u, pb0, 2);
            pb1 += __shfl_xor_sync(~0u, pb1, 1); pb1 += __shfl_xor_sync(~0u, pb1, 2);
            if (writer) {
                int m0 = mbase + wm * 32 + mi * 16 + g4;
                float2 l0 = *reinterpret_cast<const float2*>(&out[(size_t)m0 * KTOT + kA]);
                float2 l1 = *reinterpret_cast<const float2*>(&out[(size_t)(m0 + 8) * KTOT + kA]);
                *reinterpret_cast<float2*>(&out[(size_t)m0 * KTOT + kA]) =
                    make_float2(l0.x + pa0, l0.y + pb0);
                *reinterpret_cast<float2*>(&out[(size_t)(m0 + 8) * KTOT + kA]) =
                    make_float2(l1.x + pa1, l1.y + pb1);
            }
        }
    }
}

extern "C" void kernel_launch(void* const* d_in, const int* in_sizes, int n_in,
                              void* d_out, int out_size)
{
    const float* x1 = (const float*)d_in[0];
    const float* x2 = (const float*)d_in[1];
    const float* W  = (const float*)d_in[2];
    const float* P  = (const float*)d_in[3];
    const float* Q  = (const float*)d_in[4];
    float* out = (float*)d_out;

    pack_b<<<128, 256>>>(P, Q);
    pack_w<<<8, 256>>>(W);

    const int tokens = in_sizes[0] / D128;
    const int blocks = tokens / MTILE;      // 2048

    cudaFuncSetAttribute(antisym_h,
                         cudaFuncAttributeMaxDynamicSharedMemorySize, SMEM_BYTES);
    antisym_h<<<blocks, THREADS, SMEM_BYTES>>>(x1, x2, out);
}

// round 9
// speedup vs baseline: 1.1029x; 1.1029x over previous
#include <cuda_runtime.h>
#include <cuda_fp16.h>
#include <cstdint>

// AntisymmetricLayer via fp16 mma.sync.m16n8k16 (fp32 accum).
//   z = x1-x2, s = x1+x2 (fp16)
//   Phase L: lin = z @ W^T -> out (W fragment-packed per warp)
//   Main: per 4-k group, zP = z @ P^T, sQ = s @ Q^T; epilogue RMW out += sum_r zP*sQ
// r9 = r7 shape (MTILE=128, 4 warps 2Mx2N, warp tile 64x32, 2 CTAs/SM) plus:
//   - mixed grid: 888 full tiles (3 exact waves) + 272 half tiles (M=64) -> small tail
//   - B fragment LDG prefetched one k-step ahead (rotating registers)
// B fragments from L2 (packed), no cp.async, one barrier total.

#define D128 128
#define KTOT 64
#define NGRP 16
#define THREADS 128

#define ZSH 0
#define SSH 32768
#define SMEM_BYTES 65536

// fragment-packed B: [g][ks][wn][j] blocks of 512B (32 lanes x 16B = P.b0,b1,Q.b0,b1)
__device__ __align__(16) __half g_B[16 * 8 * 2 * 4 * 256];
// fragment-packed W: [ks][wn][t] blocks of 256B (32 lanes x 8B)
__device__ __align__(16) __half g_Wt[8 * 2 * 4 * 128];

__device__ __forceinline__ uint32_t smem_u32(const void* p) {
    uint32_t a;
    asm("{ .reg .u64 t; cvta.to.shared.u64 t, %1; cvt.u32.u64 %0, t; }" : "=r"(a) : "l"(p));
    return a;
}

#define LDSM_X4(r0, r1, r2, r3, a) \
    asm volatile("ldmatrix.sync.aligned.m8n8.x4.shared.b16 {%0,%1,%2,%3}, [%4];" \
        : "=r"(r0), "=r"(r1), "=r"(r2), "=r"(r3) : "r"(a))

__device__ __forceinline__ void mma_f16(float* d, const uint32_t* a, const uint32_t* b) {
    asm volatile("mma.sync.aligned.m16n8k16.row.col.f32.f16.f16.f32 "
                 "{%0,%1,%2,%3}, {%4,%5,%6,%7}, {%8,%9}, {%0,%1,%2,%3};"
                 : "+f"(d[0]), "+f"(d[1]), "+f"(d[2]), "+f"(d[3])
                 : "r"(a[0]), "r"(a[1]), "r"(a[2]), "r"(a[3]),
                   "r"(b[0]), "r"(b[1]));
}

// ---- pack P,Q into fragment order ----
__global__ void pack_b(const float* __restrict__ P, const float* __restrict__ Q) {
    int t = blockIdx.x * 256 + threadIdx.x;   // 0..32767
    int l = t & 31, j = (t >> 5) & 3, wn = (t >> 7) & 1, ks = (t >> 8) & 7, g = t >> 11;
    int c = wn * 32 + j * 8 + (l >> 2);
    int k = g * 4 + (c >> 4), r = c & 15;
    int d0 = ks * 16 + 2 * (l & 3);
    __half h[8];
    h[0] = __float2half_rn(P[(k * 128 + d0) * 16 + r]);
    h[1] = __float2half_rn(P[(k * 128 + d0 + 1) * 16 + r]);
    h[2] = __float2half_rn(P[(k * 128 + d0 + 8) * 16 + r]);
    h[3] = __float2half_rn(P[(k * 128 + d0 + 9) * 16 + r]);
    h[4] = __float2half_rn(Q[(k * 128 + d0) * 16 + r]);
    h[5] = __float2half_rn(Q[(k * 128 + d0 + 1) * 16 + r]);
    h[6] = __float2half_rn(Q[(k * 128 + d0 + 8) * 16 + r]);
    h[7] = __float2half_rn(Q[(k * 128 + d0 + 9) * 16 + r]);
    *reinterpret_cast<uint4*>(&g_B[t * 8]) = *reinterpret_cast<uint4*>(h);
}

// ---- pack W ----
__global__ void pack_w(const float* __restrict__ W) {
    int t = blockIdx.x * 256 + threadIdx.x;   // 0..2047
    int l = t & 31, tile = (t >> 5) & 3, wn = (t >> 7) & 1, ks = t >> 8;
    int n = l >> 2;
    int k = 16 * tile + 4 * (n >> 1) + 2 * wn + (n & 1);
    int d0 = ks * 16 + 2 * (l & 3);
    __half h[4];
    h[0] = __float2half_rn(W[k * 128 + d0]);
    h[1] = __float2half_rn(W[k * 128 + d0 + 1]);
    h[2] = __float2half_rn(W[k * 128 + d0 + 8]);
    h[3] = __float2half_rn(W[k * 128 + d0 + 9]);
    *reinterpret_cast<uint2*>(&g_Wt[t * 4]) = *reinterpret_cast<uint2*>(h);
}

// ---------------- tile body, MI = m16-tiles per warp (4 = full, 2 = half) ----------------
template <int MI>
__device__ __forceinline__ void tile_body(
    const float* __restrict__ x1, const float* __restrict__ x2,
    float* __restrict__ out, char* shm, uint32_t smb, size_t mbase)
{
    const int tid = threadIdx.x;
    const int lane = tid & 31;
    const int wid = tid >> 5;
    const int wm = wid & 1;
    const int wn = wid >> 1;
    const int g4 = lane >> 2;
    const int c4 = lane & 3;
    const int TT = MI * 32;   // tokens in tile

    // ---- stage z,s as fp16 (swizzled 256B rows) ----
    {
        const float4* x1v = reinterpret_cast<const float4*>(x1) + mbase * 32;
        const float4* x2v = reinterpret_cast<const float4*>(x2) + mbase * 32;
        #pragma unroll
        for (int it = 0; it < MI * 4; it++) {
            int idx = it * THREADS + tid;
            int m = idx >> 4, c = idx & 15;
            float4 a0 = x1v[m * 32 + c * 2];
            float4 a1 = x1v[m * 32 + c * 2 + 1];
            float4 b0 = x2v[m * 32 + c * 2];
            float4 b1 = x2v[m * 32 + c * 2 + 1];
            half2 zz[4], ss[4];
            zz[0] = __floats2half2_rn(a0.x - b0.x, a0.y - b0.y);
            zz[1] = __floats2half2_rn(a0.z - b0.z, a0.w - b0.w);
            zz[2] = __floats2half2_rn(a1.x - b1.x, a1.y - b1.y);
            zz[3] = __floats2half2_rn(a1.z - b1.z, a1.w - b1.w);
            ss[0] = __floats2half2_rn(a0.x + b0.x, a0.y + b0.y);
            ss[1] = __floats2half2_rn(a0.z + b0.z, a0.w + b0.w);
            ss[2] = __floats2half2_rn(a1.x + b1.x, a1.y + b1.y);
            ss[3] = __floats2half2_rn(a1.z + b1.z, a1.w + b1.w);
            uint32_t so = (uint32_t)(m * 256 + ((c ^ (m & 7)) << 4));
            *reinterpret_cast<uint4*>(shm + ZSH + so) = *reinterpret_cast<uint4*>(zz);
            *reinterpret_cast<uint4*>(shm + SSH + so) = *reinterpret_cast<uint4*>(ss);
        }
    }
    __syncthreads();

    // ---- per-lane A ldmatrix row bases ----
    const int xr = lane & 7;
    uint32_t rowA[MI];
    #pragma unroll
    for (int mi = 0; mi < MI; mi++)
        rowA[mi] = (uint32_t)((wm * (MI * 16) + mi * 16 + ((lane >> 3) & 1) * 8 + xr) * 256);
    const int krelA = lane >> 4;

    const uint4* bv = reinterpret_cast<const uint4*>(g_B);
    const uint2* wv = reinterpret_cast<const uint2*>(g_Wt);

    // ---- Phase L: lin = z @ W^T ----
    {
        float lw[MI][4][4] = {};
        #pragma unroll
        for (int ks = 0; ks < 8; ks++) {
            uint32_t offA = (uint32_t)(((2 * ks + krelA) ^ xr) << 4);
            uint32_t az[MI][4];
            #pragma unroll
            for (int mi = 0; mi < MI; mi++)
                LDSM_X4(az[mi][0], az[mi][1], az[mi][2], az[mi][3],
                        smb + ZSH + rowA[mi] + offA);
            #pragma unroll
            for (int t = 0; t < 4; t++) {
                uint2 w = wv[((ks * 2 + wn) * 4 + t) * 32 + lane];
                uint32_t bw[2] = {w.x, w.y};
                #pragma unroll
                for (int mi = 0; mi < MI; mi++)
                    mma_f16(lw[mi][t], az[mi], bw);
            }
        }
        #pragma unroll
        for (int mi = 0; mi < MI; mi++) {
            size_t m0 = mbase + wm * (MI * 16) + mi * 16 + g4;
            #pragma unroll
            for (int t = 0; t < 4; t++) {
                int k0 = 16 * t + 4 * c4 + 2 * wn;
                *reinterpret_cast<float2*>(&out[m0 * KTOT + k0]) =
                    make_float2(lw[mi][t][0], lw[mi][t][1]);
                *reinterpret_cast<float2*>(&out[(m0 + 8) * KTOT + k0]) =
                    make_float2(lw[mi][t][2], lw[mi][t][3]);
            }
        }
    }

    // ---- main loop: B prefetched one k-step ahead, no barriers ----
    uint4 v[4];
    {
        const int bb = (0 * 2 + wn) * 4;
        #pragma unroll
        for (int j = 0; j < 4; j++) v[j] = bv[(bb + j) * 32 + lane];
    }

    for (int g = 0; g < NGRP; g++) {
        float zp[MI][4][4] = {};
        float sq[MI][4][4] = {};

        #pragma unroll
        for (int ks = 0; ks < 8; ks++) {
            // prefetch next k-step's B (next group's ks=0 when ks==7)
            uint4 vn[4];
            {
                int gsn = g * 8 + ks + 1;
                if (gsn >= NGRP * 8) gsn = NGRP * 8 - 8;   // dummy reload, harmless
                const int bbn = (gsn * 2 + wn) * 4;
                #pragma unroll
                for (int j = 0; j < 4; j++) vn[j] = bv[(bbn + j) * 32 + lane];
            }

            uint32_t offA = (uint32_t)(((2 * ks + krelA) ^ xr) << 4);
            uint32_t az[MI][4], as_[MI][4];
            #pragma unroll
            for (int mi = 0; mi < MI; mi++) {
                LDSM_X4(az[mi][0], az[mi][1], az[mi][2], az[mi][3],
                        smb + ZSH + rowA[mi] + offA);
                LDSM_X4(as_[mi][0], as_[mi][1], as_[mi][2], as_[mi][3],
                        smb + SSH + rowA[mi] + offA);
            }
            #pragma unroll
            for (int j = 0; j < 4; j++) {
                uint32_t bp[2] = {v[j].x, v[j].y};
                uint32_t bq[2] = {v[j].z, v[j].w};
                #pragma unroll
                for (int mi = 0; mi < MI; mi++) {
                    mma_f16(zp[mi][j], az[mi], bp);
                    mma_f16(sq[mi][j], as_[mi], bq);
                }
            }
            #pragma unroll
            for (int j = 0; j < 4; j++) v[j] = vn[j];
        }

        // ---- epilogue: reduce r, RMW out ----
        const int kA = g * 4 + 2 * wn;
        const bool writer = (c4 == (g & 3));
        #pragma unroll
        for (int mi = 0; mi < MI; mi++) {
            float pa0 = zp[mi][0][0]*sq[mi][0][0] + zp[mi][0][1]*sq[mi][0][1]
                      + zp[mi][1][0]*sq[mi][1][0] + zp[mi][1][1]*sq[mi][1][1];
            float pa1 = zp[mi][0][2]*sq[mi][0][2] + zp[mi][0][3]*sq[mi][0][3]
                      + zp[mi][1][2]*sq[mi][1][2] + zp[mi][1][3]*sq[mi][1][3];
            float pb0 = zp[mi][2][0]*sq[mi][2][0] + zp[mi][2][1]*sq[mi][2][1]
                      + zp[mi][3][0]*sq[mi][3][0] + zp[mi][3][1]*sq[mi][3][1];
            float pb1 = zp[mi][2][2]*sq[mi][2][2] + zp[mi][2][3]*sq[mi][2][3]
                      + zp[mi][3][2]*sq[mi][3][2] + zp[mi][3][3]*sq[mi][3][3];
            pa0 += __shfl_xor_sync(~0u, pa0, 1); pa0 += __shfl_xor_sync(~0u, pa0, 2);
            pa1 += __shfl_xor_sync(~0u, pa1, 1); pa1 += __shfl_xor_sync(~0u, pa1, 2);
            pb0 += __shfl_xor_sync(~0u, pb0, 1); pb0 += __shfl_xor_sync(~0u, pb0, 2);
            pb1 += __shfl_xor_sync(~0u, pb1, 1); pb1 += __shfl_xor_sync(~0u, pb1, 2);
            if (writer) {
                size_t m0 = mbase + wm * (MI * 16) + mi * 16 + g4;
                float2 l0 = *reinterpret_cast<const float2*>(&out[m0 * KTOT + kA]);
                float2 l1 = *reinterpret_cast<const float2*>(&out[(m0 + 8) * KTOT + kA]);
                *reinterpret_cast<float2*>(&out[m0 * KTOT + kA]) =
                    make_float2(l0.x + pa0, l0.y + pb0);
                *reinterpret_cast<float2*>(&out[(m0 + 8) * KTOT + kA]) =
                    make_float2(l1.x + pa1, l1.y + pb1);
            }
        }
    }
}

// ---------------- main kernel ----------------
__global__ __launch_bounds__(THREADS, 2)
void antisym_h(const float* __restrict__ x1, const float* __restrict__ x2,
               float* __restrict__ out, int fullCTAs)
{
    extern __shared__ char shm[];
    const uint32_t smb = smem_u32(shm);
    const int bid = blockIdx.x;

    if (bid < fullCTAs) {
        tile_body<4>(x1, x2, out, shm, smb, (size_t)bid * 128);
    } else {
        tile_body<2>(x1, x2, out, shm, smb,
                     (size_t)fullCTAs * 128 + (size_t)(bid - fullCTAs) * 64);
    }
}

extern "C" void kernel_launch(void* const* d_in, const int* in_sizes, int n_in,
                              void* d_out, int out_size)
{
    const float* x1 = (const float*)d_in[0];
    const float* x2 = (const float*)d_in[1];
    const float* W  = (const float*)d_in[2];
    const float* P  = (const float*)d_in[3];
    const float* Q  = (const float*)d_in[4];
    float* out = (float*)d_out;

    pack_b<<<128, 256>>>(P, Q);
    pack_w<<<8, 256>>>(W);

    const int tokens = in_sizes[0] / D128;        // 131072
    const int tiles128 = tokens / 128;            // 1024
    const int CONC = 296;                         // 148 SMs x occ 2
    int full = (tiles128 / CONC) * CONC;          // 888
    if (full == 0) full = tiles128;
    const int smallCTAs = (tokens - full * 128) / 64;   // 272
    const int grid = full + smallCTAs;            // 1160

    cudaFuncSetAttribute(antisym_h,
                         cudaFuncAttributeMaxDynamicSharedMemorySize, SMEM_BYTES);
    antisym_h<<<grid, THREADS, SMEM_BYTES>>>(x1, x2, out, full);
}